// round 13
// baseline (speedup 1.0000x reference)
#include <cuda_runtime.h>
#include <cuda_bf16.h>
#include <cstdint>

// Problem constants
#define N_TOT   32768
#define D_DIM   256
#define K_CODES 1024
#define Q_ELEMS 8388608
#define TAU     6e-4f
#define GRID_N  296                  // 272 CTAs x 7 groups + 24 x 6 = 2048 m16-groups

// smem geometry (bytes), up-to-112-row CTA, single-buffered 64-code es
#define XP      136                  // xs pitch in b16
#define EP      264                  // es pitch in b16
#define SO_XS   0                    // 256*136*2 = 69632
#define SO_ES   69632                // 64*528    = 33792
#define SO_EN   103424               // 1024 floats
#define SO_NORM 107520               // 128 floats
#define SO_FLAG 108032               // cnt + 128 ints
#define SO_IDX  108552               // 128 ints
#define SO_RED  109064               // 8 floats
#define SO_SCR  109096               // 256 floats norm scratch
#define SMEM_TOTAL 110144

// Device scratch
__device__ float          g_enorm[K_CODES];
__device__ __nv_bfloat16  g_eb16[K_CODES * D_DIM];
__device__ float          g_partials[GRID_N];
__device__ int            g_hist[K_CODES];

__device__ __forceinline__ float warpReduceSum(float v) {
    #pragma unroll
    for (int o = 16; o > 0; o >>= 1) v += __shfl_down_sync(0xffffffffu, v, o);
    return v;
}
__device__ __forceinline__ uint32_t smem_u32(const void* p) {
    uint32_t a;
    asm("{ .reg .u64 t; cvta.to.shared.u64 t, %1; cvt.u32.u64 %0, t; }" : "=r"(a) : "l"(p));
    return a;
}
__device__ __forceinline__ uint32_t packbf(float lo, float hi) {
    return ((uint32_t)__bfloat16_as_ushort(__float2bfloat16(hi)) << 16)
         |  (uint32_t)__bfloat16_as_ushort(__float2bfloat16(lo));
}

#define LDM_X4_T(r0,r1,r2,r3, a)                                               \
    asm volatile("ldmatrix.sync.aligned.m8n8.x4.trans.shared.b16 {%0,%1,%2,%3}, [%4];" \
                 : "=r"(r0), "=r"(r1), "=r"(r2), "=r"(r3) : "r"(a))
#define LDM_X4(r0,r1,r2,r3, a)                                                 \
    asm volatile("ldmatrix.sync.aligned.m8n8.x4.shared.b16 {%0,%1,%2,%3}, [%4];" \
                 : "=r"(r0), "=r"(r1), "=r"(r2), "=r"(r3) : "r"(a))
#define MMA_BF16(c0,c1,c2,c3, a0,a1,a2,a3, b0,b1)                              \
    asm volatile("mma.sync.aligned.m16n8k16.row.col.f32.bf16.bf16.f32 "        \
                 "{%0,%1,%2,%3},{%4,%5,%6,%7},{%8,%9},{%0,%1,%2,%3};"          \
                 : "+f"(c0), "+f"(c1), "+f"(c2), "+f"(c3)                      \
                 : "r"(a0), "r"(a1), "r"(a2), "r"(a3), "r"(b0), "r"(b1))
#define CP_ASYNC16(dst, src)                                                   \
    asm volatile("cp.async.cg.shared.global [%0], [%1], 16;" :: "r"(dst), "l"(src))
#define CP_COMMIT() asm volatile("cp.async.commit_group;" ::: "memory")
#define CP_WAIT(n)  asm volatile("cp.async.wait_group %0;" :: "n"(n) : "memory")

__device__ __forceinline__ void ins4(float v, int k, float bv[4], int bi[4]) {
    if (v < bv[3] || (v == bv[3] && k < bi[3])) {
        bv[3] = v; bi[3] = k;
        #pragma unroll
        for (int t = 3; t > 0; t--) {
            if (bv[t] < bv[t-1] || (bv[t] == bv[t-1] && bi[t] < bi[t-1])) {
                float tv = bv[t]; bv[t] = bv[t-1]; bv[t-1] = tv;
                int   ti = bi[t]; bi[t] = bi[t-1]; bi[t-1] = ti;
            }
        }
    }
}

// ---------------------------------------------------------------------------
// 1) prep: ||e_k||^2 + e->bf16 + zero hist. grid=1024, block=256
// ---------------------------------------------------------------------------
__global__ void prep_kernel(const float* __restrict__ emb) {
    __shared__ float red[8];
    int k = blockIdx.x;
    float v = emb[k * D_DIM + threadIdx.x];
    g_eb16[k * D_DIM + threadIdx.x] = __float2bfloat16(v);
    float s = v * v;
    s = warpReduceSum(s);
    if ((threadIdx.x & 31) == 0) red[threadIdx.x >> 5] = s;
    __syncthreads();
    if (threadIdx.x < 8) {
        float t = red[threadIdx.x];
        #pragma unroll
        for (int o = 4; o > 0; o >>= 1) t += __shfl_down_sync(0xffu, t, o);
        if (threadIdx.x == 0) g_enorm[k] = t;
    }
    if (blockIdx.x == 0) {
        for (int i = threadIdx.x; i < K_CODES; i += 256) g_hist[i] = 0;
    }
}

// ---------------------------------------------------------------------------
// 2) bf16 mma.sync GEMM + best-4/lane + fused exact rescue + gather/SSE/hist.
//    Mixed tiles: 272 CTAs x 112 rows + 24 x 96 (balanced one-wave, 2 CTA/SM).
//    8 warps; warp w computes row group w when w < ngroups (else staging only).
// ---------------------------------------------------------------------------
__global__ void __launch_bounds__(256, 2)
argmin_bf16_kernel(const float* __restrict__ x, const float* __restrict__ embf,
                   float* __restrict__ out, int out_size) {
    extern __shared__ __align__(16) char smem[];
    __nv_bfloat16* xs = (__nv_bfloat16*)(smem + SO_XS);   // [256 d][XP]
    float* en_s  = (float*)(smem + SO_EN);
    float* norms = (float*)(smem + SO_NORM);
    int*   flagc = (int*)(smem + SO_FLAG);
    int*   flagr = flagc + 1;
    int*   idx_s = (int*)(smem + SO_IDX);

    const int tid  = threadIdx.x;
    const int lane = tid & 31;
    const int w    = tid >> 5;           // 0..7 = row group
    const int g4   = lane >> 2;
    const int tg   = lane & 3;
    const int R    = w << 4;
    const int bid  = blockIdx.x;
    const int ng   = (bid < 272) ? 7 : 6;
    const int n0   = ((bid < 272) ? (7 * bid) : (1904 + 6 * (bid - 272))) << 4;
    const int rows = ng << 4;
    const bool act = (w < ng);           // warp computes MMA

    const uint32_t es_u = smem_u32(smem + SO_ES);

    // ---- prologue: stage chunk 0 (64 codes) via cp.async
    #pragma unroll
    for (int it = 0; it < 8; it++) {
        int lin = it * 256 + tid;        // 0..2047
        int c   = lin >> 5;
        int sg  = lin & 31;
        CP_ASYNC16(es_u + (uint32_t)(c * (EP * 2) + sg * 16),
                   (const void*)(g_eb16 + ((size_t)c << 8) + sg * 8));
    }
    CP_COMMIT();
    if (tid == 0) *flagc = 0;

    // ---- fill xs (bf16, [d][row]); 8-row chunks never straddle a batch edge
    #pragma unroll
    for (int i = 0; i < 16; i++) {
        int lin = i * 256 + tid;         // 0..4095
        int d   = lin >> 4;
        int r8  = (lin & 15) << 3;       // 0..120
        int r8c = (r8 < rows) ? r8 : (rows - 8);   // clamp (duplicate fill)
        int nc  = n0 + r8c;
        const float* p = x + (((size_t)(nc >> 10)) << 18) + ((size_t)d << 10) + (nc & 1023);
        float4 t0 = *(const float4*)(p);
        float4 t1 = *(const float4*)(p + 4);
        uint4 u;
        u.x = packbf(t0.x, t0.y); u.y = packbf(t0.z, t0.w);
        u.z = packbf(t1.x, t1.y); u.w = packbf(t1.z, t1.w);
        *(uint4*)&xs[d * XP + r8c] = u;
    }
    // ---- exact fp32 row norms: half-row per thread
    {
        int r = tid & 127;
        int h = tid >> 7;                // 0..1 (128 d each)
        if (r < rows) {
            int nr = n0 + r;
            const float* p = x + (((size_t)(nr >> 10)) << 18)
                               + (((size_t)(h << 7)) << 10) + (nr & 1023);
            float a = 0.f;
            #pragma unroll 8
            for (int d = 0; d < 128; d++) a = fmaf(p[(size_t)d << 10], p[(size_t)d << 10], a);
            ((float*)(smem + SO_SCR))[tid] = a;
        }
    }
    for (int i = tid; i < K_CODES; i += 256) en_s[i] = g_enorm[i];
    __syncthreads();
    if (tid < rows) {
        const float* sc = (const float*)(smem + SO_SCR);
        norms[tid] = sc[tid] + sc[tid + 128];
    }
    CP_WAIT(0);
    __syncthreads();

    const float na0 = act ? norms[R + g4] : 0.f;
    const float na1 = act ? norms[R + g4 + 8] : 0.f;

    // per-lane ldmatrix addressing
    const uint32_t xs_u = smem_u32(xs);
    const int i8  = lane & 7;
    const int sel = lane >> 3;
    const uint32_t a_base = xs_u
        + (uint32_t)(((i8 + ((sel & 2) ? 8 : 0)) * XP + R + ((sel & 1) ? 8 : 0)) * 2);
    uint32_t b_off[4];
    #pragma unroll
    for (int p = 0; p < 4; p++)
        b_off[p] = (uint32_t)(((p * 16 + i8 + ((sel & 2) ? 8 : 0)) * EP) * 2
                              + ((sel & 1) ? 16 : 0));

    float bva[4], bvb[4]; int bia[4], bib[4];
    #pragma unroll
    for (int j = 0; j < 4; j++) {
        bva[j] = 3.4e38f; bvb[j] = 3.4e38f;
        bia[j] = 0x7fffffff; bib[j] = 0x7fffffff;
    }

    for (int chunk = 0; chunk < 16; chunk++) {
        float acc[8][4];
        #pragma unroll
        for (int j = 0; j < 8; j++)
            #pragma unroll
            for (int q = 0; q < 4; q++) acc[j][q] = 0.f;

        if (act) {
            #pragma unroll
            for (int K = 0; K < 256; K += 16) {
                uint32_t a0, a1, a2, a3;
                LDM_X4_T(a0, a1, a2, a3, a_base + (uint32_t)(K * XP * 2));
                #pragma unroll
                for (int p = 0; p < 4; p++) {
                    uint32_t r0, r1, r2, r3;
                    LDM_X4(r0, r1, r2, r3, es_u + b_off[p] + (uint32_t)(K * 2));
                    MMA_BF16(acc[2*p][0], acc[2*p][1], acc[2*p][2], acc[2*p][3],
                             a0, a1, a2, a3, r0, r1);
                    MMA_BF16(acc[2*p+1][0], acc[2*p+1][1], acc[2*p+1][2], acc[2*p+1][3],
                             a0, a1, a2, a3, r2, r3);
                }
            }
        }
        __syncthreads();   // all warps done reading es before restage
        if (chunk < 15) {  // stage next chunk (single buffer)
            #pragma unroll
            for (int it = 0; it < 8; it++) {
                int lin = it * 256 + tid;
                int c   = lin >> 5;
                int sg  = lin & 31;
                CP_ASYNC16(es_u + (uint32_t)(c * (EP * 2) + sg * 16),
                           (const void*)(g_eb16 + (((size_t)((chunk + 1) * 64 + c)) << 8) + sg * 8));
            }
            CP_COMMIT();
        }
        // epilogue overlaps the cp.async in flight
        if (act) {
            const int kb = chunk * 64;
            #pragma unroll
            for (int j = 0; j < 8; j++) {
                int k0 = kb + (j >> 1) * 16 + (j & 1) * 8 + 2 * tg;
                float e0 = en_s[k0], e1 = en_s[k0 + 1];
                ins4(fmaf(-2.f, acc[j][0], na0 + e0), k0,     bva, bia);
                ins4(fmaf(-2.f, acc[j][1], na0 + e1), k0 + 1, bva, bia);
                ins4(fmaf(-2.f, acc[j][2], na1 + e0), k0,     bvb, bib);
                ins4(fmaf(-2.f, acc[j][3], na1 + e1), k0 + 1, bvb, bib);
            }
        }
        if (chunk < 15) CP_WAIT(0);
        __syncthreads();
    }

    // ---- candidate staging (alias es; all MMA reads done) ----
    float* cand_v = (float*)(smem + SO_ES);              // [128][16]
    int*   cand_i = (int*)(smem + SO_ES + 8192);
    if (act) {
        int ra = R + g4, rb = R + g4 + 8;
        int s0 = tg * 4;
        #pragma unroll
        for (int j = 0; j < 4; j++) {
            cand_v[ra * 16 + s0 + j] = bva[j];
            cand_i[ra * 16 + s0 + j] = bia[j];
            cand_v[rb * 16 + s0 + j] = bvb[j];
            cand_i[rb * 16 + s0 + j] = bib[j];
        }
    }
    __syncthreads();

    // ---- decision per row ----
    if (tid < rows) {
        int r = tid;
        float vm = cand_v[r * 16]; int im = cand_i[r * 16];
        #pragma unroll
        for (int j = 1; j < 16; j++) {
            float v = cand_v[r * 16 + j]; int k = cand_i[r * 16 + j];
            if (v < vm || (v == vm && k < im)) { vm = v; im = k; }
        }
        int cnt = 0;
        #pragma unroll
        for (int j = 0; j < 16; j++) cnt += (cand_v[r * 16 + j] <= vm + TAU);
        if (cnt == 1) {
            idx_s[r] = im;
        } else {
            int slot = atomicAdd(flagc, 1);
            flagr[slot] = r;
        }
    }
    __syncthreads();

    // ---- fused exact rescue: warp per flagged row ----
    const int nflag = *flagc;
    for (int f = w; f < nflag; f += 8) {
        int r = flagr[f];
        int nr = n0 + r;
        const float* xr = x + (((size_t)(nr >> 10)) << 18) + (nr & 1023);
        float xv[8];
        #pragma unroll
        for (int t = 0; t < 8; t++) xv[t] = xr[(size_t)(lane + (t << 5)) << 10];
        float a = norms[r];   // exact fp32 (translation-invariant vs reference)

        float vmin = cand_v[r * 16];
        #pragma unroll
        for (int j = 1; j < 16; j++) vmin = fminf(vmin, cand_v[r * 16 + j]);

        float bestv = 3.4e38f; int besti = 0x7fffffff;
        for (int j = 0; j < 16; j++) {
            float cv = cand_v[r * 16 + j];
            if (cv > vmin + TAU) continue;
            int k = cand_i[r * 16 + j];
            const float* er = embf + ((size_t)k << 8);
            float d = 0.f;
            #pragma unroll
            for (int t = 0; t < 8; t++) d = fmaf(xv[t], er[lane + (t << 5)], d);
            #pragma unroll
            for (int o = 16; o > 0; o >>= 1) d += __shfl_xor_sync(0xffffffffu, d, o);
            float vv = fmaf(-2.f, d, a + en_s[k]);   // fl(fl(a+b) - 2*dot)
            if (vv < bestv || (vv == bestv && k < besti)) { bestv = vv; besti = k; }
        }
        if (lane == 0) idx_s[r] = besti;
    }
    __syncthreads();

    // ---- fused hist + index writeout ----
    if (tid < rows) {
        int idx = idx_s[tid];
        atomicAdd(&g_hist[idx], 1);
        if (out_size >= Q_ELEMS + 2 + N_TOT)
            out[Q_ELEMS + 2 + n0 + tid] = (float)idx;
    }

    // ---- fused gather + SSE for this CTA's rows ----
    float sse = 0.f;
    #pragma unroll
    for (int u = 0; u < 32; u++) {
        int lin = u * 256 + tid;          // 0..8191
        int r   = lin & 127;
        int d4  = lin >> 7;               // 0..63
        if (r < rows) {
            int nr  = n0 + r;
            int br  = nr >> 10;
            int hwr = nr & 1023;
            int idx = idx_s[r];
            float4 q = *(const float4*)(embf + ((size_t)idx << 8) + (d4 << 2));
            const float* xp = x + (((size_t)br) << 18) + (((size_t)(d4 << 2)) << 10) + hwr;
            float* op = out + (((size_t)br) << 18) + (((size_t)(d4 << 2)) << 10) + hwr;
            float qv[4] = {q.x, q.y, q.z, q.w};
            #pragma unroll
            for (int j = 0; j < 4; j++) {
                float xvj = xp[(size_t)j << 10];
                op[(size_t)j << 10] = qv[j];
                float dd = qv[j] - xvj;
                sse = fmaf(dd, dd, sse);
            }
        }
    }
    {
        float* red = (float*)(smem + SO_RED);
        sse = warpReduceSum(sse);
        if (lane == 0) red[w] = sse;
        __syncthreads();
        if (tid < 8) {
            float v = red[tid];
            #pragma unroll
            for (int o = 4; o > 0; o >>= 1) v += __shfl_down_sync(0xffu, v, o);
            if (tid == 0) g_partials[blockIdx.x] = v;
        }
    }
}

// ---------------------------------------------------------------------------
// 3) finalize: loss + perplexity. grid=1, block=1024
// ---------------------------------------------------------------------------
__global__ void finalize_kernel(float* __restrict__ out, int out_size) {
    __shared__ float red[32];
    int tid = threadIdx.x;
    float s = (tid < GRID_N) ? g_partials[tid] : 0.f;
    s = warpReduceSum(s);
    if ((tid & 31) == 0) red[tid >> 5] = s;
    __syncthreads();
    if (tid < 32) {
        float v = red[tid];
        v = warpReduceSum(v);
        if (tid == 0 && out_size > Q_ELEMS)
            out[Q_ELEMS] = 1.25f * v / (float)Q_ELEMS;   // q_latent + 0.25*e_latent
    }
    __syncthreads();
    float p = (float)g_hist[tid] / (float)N_TOT;
    float t = -p * logf(p + 1e-10f);
    t = warpReduceSum(t);
    if ((tid & 31) == 0) red[tid >> 5] = t;
    __syncthreads();
    if (tid < 32) {
        float v = red[tid];
        v = warpReduceSum(v);
        if (tid == 0 && out_size > Q_ELEMS + 1)
            out[Q_ELEMS + 1] = expf(v);
    }
}

// ---------------------------------------------------------------------------
extern "C" void kernel_launch(void* const* d_in, const int* in_sizes, int n_in,
                              void* d_out, int out_size) {
    const float* inputs = (const float*)d_in[0];
    const float* emb    = (const float*)d_in[1];
    if (n_in >= 2 && in_sizes[0] == K_CODES * D_DIM && in_sizes[1] == Q_ELEMS) {
        const float* t = inputs; inputs = emb; emb = t;
    }
    float* out = (float*)d_out;

    cudaFuncSetAttribute(argmin_bf16_kernel,
                         cudaFuncAttributeMaxDynamicSharedMemorySize, SMEM_TOTAL);

    prep_kernel<<<K_CODES, 256>>>(emb);
    argmin_bf16_kernel<<<GRID_N, 256, SMEM_TOTAL>>>(inputs, emb, out, out_size);
    finalize_kernel<<<1, 1024>>>(out, out_size);
}

// round 14
// speedup vs baseline: 1.3035x; 1.3035x over previous
#include <cuda_runtime.h>
#include <cuda_bf16.h>
#include <cstdint>

// Problem constants
#define N_TOT   32768
#define D_DIM   256
#define K_CODES 1024
#define Q_ELEMS 8388608
#define TAU     6e-4f

// smem geometry (bytes), 128-row CTA, double-buffered 32-code es
#define XP      136                  // xs pitch in b16 (272B, 16B-aligned rows)
#define EP      264                  // es pitch in b16 (528B)
#define ES_BUF  16896                // 32 codes * 528
#define SO_XS   0                    // 256*136*2 = 69632
#define SO_ES   69632                // 2 * 16896 = 33792
#define SO_EN   103424               // 1024 floats
#define SO_NORM 107520               // 128 floats
#define SO_FLAG 108032               // cnt + 128 ints
#define SO_IDX  108552               // 128 ints
#define SO_RED  109064               // 8 floats
#define SO_SCR  109096               // 256 floats norm scratch
#define SMEM_TOTAL 110144

// Device scratch
__device__ float          g_enorm[K_CODES];
__device__ __nv_bfloat16  g_eb16[K_CODES * D_DIM];
__device__ float          g_partials[256];
__device__ int            g_hist[K_CODES];

__device__ __forceinline__ float warpReduceSum(float v) {
    #pragma unroll
    for (int o = 16; o > 0; o >>= 1) v += __shfl_down_sync(0xffffffffu, v, o);
    return v;
}
__device__ __forceinline__ uint32_t smem_u32(const void* p) {
    uint32_t a;
    asm("{ .reg .u64 t; cvta.to.shared.u64 t, %1; cvt.u32.u64 %0, t; }" : "=r"(a) : "l"(p));
    return a;
}
__device__ __forceinline__ uint32_t packbf(float lo, float hi) {
    return ((uint32_t)__bfloat16_as_ushort(__float2bfloat16(hi)) << 16)
         |  (uint32_t)__bfloat16_as_ushort(__float2bfloat16(lo));
}

#define LDM_X4_T(r0,r1,r2,r3, a)                                               \
    asm volatile("ldmatrix.sync.aligned.m8n8.x4.trans.shared.b16 {%0,%1,%2,%3}, [%4];" \
                 : "=r"(r0), "=r"(r1), "=r"(r2), "=r"(r3) : "r"(a))
#define LDM_X4(r0,r1,r2,r3, a)                                                 \
    asm volatile("ldmatrix.sync.aligned.m8n8.x4.shared.b16 {%0,%1,%2,%3}, [%4];" \
                 : "=r"(r0), "=r"(r1), "=r"(r2), "=r"(r3) : "r"(a))
#define MMA_BF16(c0,c1,c2,c3, a0,a1,a2,a3, b0,b1)                              \
    asm volatile("mma.sync.aligned.m16n8k16.row.col.f32.bf16.bf16.f32 "        \
                 "{%0,%1,%2,%3},{%4,%5,%6,%7},{%8,%9},{%0,%1,%2,%3};"          \
                 : "+f"(c0), "+f"(c1), "+f"(c2), "+f"(c3)                      \
                 : "r"(a0), "r"(a1), "r"(a2), "r"(a3), "r"(b0), "r"(b1))
#define CP_ASYNC16(dst, src)                                                   \
    asm volatile("cp.async.cg.shared.global [%0], [%1], 16;" :: "r"(dst), "l"(src))
#define CP_COMMIT() asm volatile("cp.async.commit_group;" ::: "memory")
#define CP_WAIT(n)  asm volatile("cp.async.wait_group %0;" :: "n"(n) : "memory")

__device__ __forceinline__ void ins4(float v, int k, float bv[4], int bi[4]) {
    if (v < bv[3] || (v == bv[3] && k < bi[3])) {
        bv[3] = v; bi[3] = k;
        #pragma unroll
        for (int t = 3; t > 0; t--) {
            if (bv[t] < bv[t-1] || (bv[t] == bv[t-1] && bi[t] < bi[t-1])) {
                float tv = bv[t]; bv[t] = bv[t-1]; bv[t-1] = tv;
                int   ti = bi[t]; bi[t] = bi[t-1]; bi[t-1] = ti;
            }
        }
    }
}

// ---------------------------------------------------------------------------
// 1) prep: ||e_k||^2 + e->bf16 + zero hist. grid=1024, block=256
// ---------------------------------------------------------------------------
__global__ void prep_kernel(const float* __restrict__ emb) {
    __shared__ float red[8];
    int k = blockIdx.x;
    float v = emb[k * D_DIM + threadIdx.x];
    g_eb16[k * D_DIM + threadIdx.x] = __float2bfloat16(v);
    float s = v * v;
    s = warpReduceSum(s);
    if ((threadIdx.x & 31) == 0) red[threadIdx.x >> 5] = s;
    __syncthreads();
    if (threadIdx.x < 8) {
        float t = red[threadIdx.x];
        #pragma unroll
        for (int o = 4; o > 0; o >>= 1) t += __shfl_down_sync(0xffu, t, o);
        if (threadIdx.x == 0) g_enorm[k] = t;
    }
    if (blockIdx.x == 0) {
        for (int i = threadIdx.x; i < K_CODES; i += 256) g_hist[i] = 0;
    }
}

// ---------------------------------------------------------------------------
// 2) bf16 mma.sync GEMM + best-4/lane + fused exact rescue + gather/SSE/hist.
//    CTA: 128 rows x 1024 codes (32 chunks of 32 codes, DOUBLE-buffered es:
//    staging issued one full chunk ahead -> copy latency fully hidden).
//    8 warps = 8 row-groups of 16. grid=256, block=256, 2 CTA/SM -> one wave.
// ---------------------------------------------------------------------------
__global__ void __launch_bounds__(256, 2)
argmin_bf16_kernel(const float* __restrict__ x, const float* __restrict__ embf,
                   float* __restrict__ out, int out_size) {
    extern __shared__ __align__(16) char smem[];
    __nv_bfloat16* xs = (__nv_bfloat16*)(smem + SO_XS);   // [256 d][XP]
    float* en_s  = (float*)(smem + SO_EN);
    float* norms = (float*)(smem + SO_NORM);
    int*   flagc = (int*)(smem + SO_FLAG);
    int*   flagr = flagc + 1;
    int*   idx_s = (int*)(smem + SO_IDX);

    const int tid  = threadIdx.x;
    const int lane = tid & 31;
    const int w    = tid >> 5;           // 0..7 = row group
    const int g4   = lane >> 2;
    const int tg   = lane & 3;
    const int R    = w << 4;
    const int n0   = blockIdx.x << 7;
    const int b    = n0 >> 10;
    const int hw0  = n0 & 1023;
    const float* xb = x + ((size_t)b << 18) + hw0;

    const uint32_t es_u = smem_u32(smem + SO_ES);

    // ---- prologue: stage chunks 0 and 1 (32 codes each) via cp.async
    #pragma unroll
    for (int it = 0; it < 4; it++) {
        int lin = it * 256 + tid;        // 0..1023
        int c   = lin >> 5;              // code 0..31
        int sg  = lin & 31;              // 16B segment
        CP_ASYNC16(es_u + (uint32_t)(c * (EP * 2) + sg * 16),
                   (const void*)(g_eb16 + ((size_t)c << 8) + sg * 8));
    }
    CP_COMMIT();
    #pragma unroll
    for (int it = 0; it < 4; it++) {
        int lin = it * 256 + tid;
        int c   = lin >> 5;
        int sg  = lin & 31;
        CP_ASYNC16(es_u + (uint32_t)(ES_BUF + c * (EP * 2) + sg * 16),
                   (const void*)(g_eb16 + ((size_t)(32 + c) << 8) + sg * 8));
    }
    CP_COMMIT();
    if (tid == 0) *flagc = 0;

    // ---- fill xs (bf16, [d][row]) ----
    #pragma unroll
    for (int i = 0; i < 16; i++) {
        int lin = i * 256 + tid;         // 0..4095
        int d   = lin >> 4;
        int r8  = (lin & 15) << 3;
        float4 t0 = *(const float4*)(xb + ((size_t)d << 10) + r8);
        float4 t1 = *(const float4*)(xb + ((size_t)d << 10) + r8 + 4);
        uint4 u;
        u.x = packbf(t0.x, t0.y); u.y = packbf(t0.z, t0.w);
        u.z = packbf(t1.x, t1.y); u.w = packbf(t1.z, t1.w);
        *(uint4*)&xs[d * XP + r8] = u;
    }
    // ---- exact fp32 row norms: half-row per thread, dedicated scratch
    {
        int row = tid & 127;
        int h   = tid >> 7;              // 0..1 (128 d each)
        float a = 0.f;
        const float* p = xb + ((size_t)(h << 7) << 10) + row;
        #pragma unroll 8
        for (int d = 0; d < 128; d++) a = fmaf(p[(size_t)d << 10], p[(size_t)d << 10], a);
        ((float*)(smem + SO_SCR))[tid] = a;
    }
    for (int i = tid; i < K_CODES; i += 256) en_s[i] = g_enorm[i];
    __syncthreads();
    if (tid < 128) {
        const float* sc = (const float*)(smem + SO_SCR);
        norms[tid] = sc[tid] + sc[tid + 128];
    }
    __syncthreads();

    const float na0 = norms[R + g4];
    const float na1 = norms[R + g4 + 8];

    // per-lane ldmatrix addressing
    const uint32_t xs_u = smem_u32(xs);
    const int i8  = lane & 7;
    const int sel = lane >> 3;
    const uint32_t a_base = xs_u
        + (uint32_t)(((i8 + ((sel & 2) ? 8 : 0)) * XP + R + ((sel & 1) ? 8 : 0)) * 2);
    uint32_t b_off[2];
    #pragma unroll
    for (int p = 0; p < 2; p++)
        b_off[p] = (uint32_t)(((p * 16 + i8 + ((sel & 2) ? 8 : 0)) * EP) * 2
                              + ((sel & 1) ? 16 : 0));

    float bva[4], bvb[4]; int bia[4], bib[4];
    #pragma unroll
    for (int j = 0; j < 4; j++) {
        bva[j] = 3.4e38f; bvb[j] = 3.4e38f;
        bia[j] = 0x7fffffff; bib[j] = 0x7fffffff;
    }

    for (int chunk = 0; chunk < 32; chunk++) {
        const uint32_t eb = es_u + (uint32_t)((chunk & 1) * ES_BUF);
        CP_WAIT(1);        // current chunk's buffer complete (next may be in flight)
        __syncthreads();

        float acc[4][4];
        #pragma unroll
        for (int j = 0; j < 4; j++)
            #pragma unroll
            for (int q = 0; q < 4; q++) acc[j][q] = 0.f;

        #pragma unroll
        for (int K = 0; K < 256; K += 16) {
            uint32_t a0, a1, a2, a3;
            LDM_X4_T(a0, a1, a2, a3, a_base + (uint32_t)(K * XP * 2));
            #pragma unroll
            for (int p = 0; p < 2; p++) {
                uint32_t r0, r1, r2, r3;
                LDM_X4(r0, r1, r2, r3, eb + b_off[p] + (uint32_t)(K * 2));
                MMA_BF16(acc[2*p][0], acc[2*p][1], acc[2*p][2], acc[2*p][3],
                         a0, a1, a2, a3, r0, r1);
                MMA_BF16(acc[2*p+1][0], acc[2*p+1][1], acc[2*p+1][2], acc[2*p+1][3],
                         a0, a1, a2, a3, r2, r3);
            }
        }
        __syncthreads();   // all warps done reading this buffer
        if (chunk + 2 < 32) {   // stage chunk+2 into the buffer just freed
            #pragma unroll
            for (int it = 0; it < 4; it++) {
                int lin = it * 256 + tid;
                int c   = lin >> 5;
                int sg  = lin & 31;
                CP_ASYNC16(eb + (uint32_t)(c * (EP * 2) + sg * 16),
                           (const void*)(g_eb16 + (((size_t)((chunk + 2) * 32 + c)) << 8) + sg * 8));
            }
            CP_COMMIT();
        }
        // epilogue overlaps the in-flight copy
        const int kb = chunk * 32;
        #pragma unroll
        for (int j = 0; j < 4; j++) {
            int k0 = kb + (j >> 1) * 16 + (j & 1) * 8 + 2 * tg;
            float e0 = en_s[k0], e1 = en_s[k0 + 1];
            ins4(fmaf(-2.f, acc[j][0], na0 + e0), k0,     bva, bia);
            ins4(fmaf(-2.f, acc[j][1], na0 + e1), k0 + 1, bva, bia);
            ins4(fmaf(-2.f, acc[j][2], na1 + e0), k0,     bvb, bib);
            ins4(fmaf(-2.f, acc[j][3], na1 + e1), k0 + 1, bvb, bib);
        }
    }

    __syncthreads();
    // ---- candidate staging (alias es; all MMA reads done) ----
    float* cand_v = (float*)(smem + SO_ES);              // [128][16]
    int*   cand_i = (int*)(smem + SO_ES + 8192);
    {
        int ra = R + g4, rb = R + g4 + 8;
        int s0 = tg * 4;
        #pragma unroll
        for (int j = 0; j < 4; j++) {
            cand_v[ra * 16 + s0 + j] = bva[j];
            cand_i[ra * 16 + s0 + j] = bia[j];
            cand_v[rb * 16 + s0 + j] = bvb[j];
            cand_i[rb * 16 + s0 + j] = bib[j];
        }
    }
    __syncthreads();

    // ---- decision per row ----
    if (tid < 128) {
        int r = tid;
        float vm = cand_v[r * 16]; int im = cand_i[r * 16];
        #pragma unroll
        for (int j = 1; j < 16; j++) {
            float v = cand_v[r * 16 + j]; int k = cand_i[r * 16 + j];
            if (v < vm || (v == vm && k < im)) { vm = v; im = k; }
        }
        int cnt = 0;
        #pragma unroll
        for (int j = 0; j < 16; j++) cnt += (cand_v[r * 16 + j] <= vm + TAU);
        if (cnt == 1) {
            idx_s[r] = im;
        } else {
            int slot = atomicAdd(flagc, 1);
            flagr[slot] = r;
        }
    }
    __syncthreads();

    // ---- fused exact rescue: warp per flagged row ----
    const int nflag = *flagc;
    for (int f = w; f < nflag; f += 8) {
        int r = flagr[f];
        const float* xr = xb + r;
        float xv[8];
        #pragma unroll
        for (int t = 0; t < 8; t++) xv[t] = xr[(size_t)(lane + (t << 5)) << 10];
        float a = norms[r];   // exact fp32 (translation-invariant vs reference)

        float vmin = cand_v[r * 16];
        #pragma unroll
        for (int j = 1; j < 16; j++) vmin = fminf(vmin, cand_v[r * 16 + j]);

        float bestv = 3.4e38f; int besti = 0x7fffffff;
        for (int j = 0; j < 16; j++) {
            float cv = cand_v[r * 16 + j];
            if (cv > vmin + TAU) continue;
            int k = cand_i[r * 16 + j];
            const float* er = embf + ((size_t)k << 8);
            float d = 0.f;
            #pragma unroll
            for (int t = 0; t < 8; t++) d = fmaf(xv[t], er[lane + (t << 5)], d);
            #pragma unroll
            for (int o = 16; o > 0; o >>= 1) d += __shfl_xor_sync(0xffffffffu, d, o);
            float vv = fmaf(-2.f, d, a + en_s[k]);   // fl(fl(a+b) - 2*dot)
            if (vv < bestv || (vv == bestv && k < besti)) { bestv = vv; besti = k; }
        }
        if (lane == 0) idx_s[r] = besti;
    }
    __syncthreads();

    // ---- fused hist + index writeout ----
    if (tid < 128) {
        int idx = idx_s[tid];
        atomicAdd(&g_hist[idx], 1);
        if (out_size >= Q_ELEMS + 2 + N_TOT)
            out[Q_ELEMS + 2 + n0 + tid] = (float)idx;
    }

    // ---- fused gather + SSE for this CTA's 128 rows ----
    float sse = 0.f;
    #pragma unroll
    for (int u = 0; u < 32; u++) {
        int lin = u * 256 + tid;          // 0..8191
        int r   = lin & 127;
        int d4  = lin >> 7;               // 0..63
        int idx = idx_s[r];
        float4 q = *(const float4*)(embf + ((size_t)idx << 8) + (d4 << 2));
        const float* xp = xb + ((size_t)(d4 << 2) << 10) + r;
        float* op = out + ((size_t)b << 18) + ((size_t)(d4 << 2) << 10) + hw0 + r;
        float qv[4] = {q.x, q.y, q.z, q.w};
        #pragma unroll
        for (int j = 0; j < 4; j++) {
            float xvj = xp[(size_t)j << 10];
            op[(size_t)j << 10] = qv[j];
            float dd = qv[j] - xvj;
            sse = fmaf(dd, dd, sse);
        }
    }
    {
        float* red = (float*)(smem + SO_RED);
        sse = warpReduceSum(sse);
        if (lane == 0) red[w] = sse;
        __syncthreads();
        if (tid < 8) {
            float v = red[tid];
            #pragma unroll
            for (int o = 4; o > 0; o >>= 1) v += __shfl_down_sync(0xffu, v, o);
            if (tid == 0) g_partials[blockIdx.x] = v;
        }
    }
}

// ---------------------------------------------------------------------------
// 3) finalize: loss + perplexity. grid=1, block=1024
// ---------------------------------------------------------------------------
__global__ void finalize_kernel(float* __restrict__ out, int out_size) {
    __shared__ float red[32];
    int tid = threadIdx.x;
    float s = (tid < 256) ? g_partials[tid] : 0.f;
    s = warpReduceSum(s);
    if ((tid & 31) == 0) red[tid >> 5] = s;
    __syncthreads();
    if (tid < 32) {
        float v = red[tid];
        v = warpReduceSum(v);
        if (tid == 0 && out_size > Q_ELEMS)
            out[Q_ELEMS] = 1.25f * v / (float)Q_ELEMS;   // q_latent + 0.25*e_latent
    }
    __syncthreads();
    float p = (float)g_hist[tid] / (float)N_TOT;
    float t = -p * logf(p + 1e-10f);
    t = warpReduceSum(t);
    if ((tid & 31) == 0) red[tid >> 5] = t;
    __syncthreads();
    if (tid < 32) {
        float v = red[tid];
        v = warpReduceSum(v);
        if (tid == 0 && out_size > Q_ELEMS + 1)
            out[Q_ELEMS + 1] = expf(v);
    }
}

// ---------------------------------------------------------------------------
extern "C" void kernel_launch(void* const* d_in, const int* in_sizes, int n_in,
                              void* d_out, int out_size) {
    const float* inputs = (const float*)d_in[0];
    const float* emb    = (const float*)d_in[1];
    if (n_in >= 2 && in_sizes[0] == K_CODES * D_DIM && in_sizes[1] == Q_ELEMS) {
        const float* t = inputs; inputs = emb; emb = t;
    }
    float* out = (float*)d_out;

    cudaFuncSetAttribute(argmin_bf16_kernel,
                         cudaFuncAttributeMaxDynamicSharedMemorySize, SMEM_TOTAL);

    prep_kernel<<<K_CODES, 256>>>(emb);
    argmin_bf16_kernel<<<N_TOT / 128, 256, SMEM_TOTAL>>>(inputs, emb, out, out_size);
    finalize_kernel<<<1, 1024>>>(out, out_size);
}

// round 15
// speedup vs baseline: 1.4737x; 1.1306x over previous
#include <cuda_runtime.h>
#include <cuda_bf16.h>
#include <cstdint>

// Problem constants
#define N_TOT   32768
#define D_DIM   256
#define K_CODES 1024
#define Q_ELEMS 8388608
#define TAU     6e-4f

// smem geometry (bytes), 128-row CTA, single-buffered 64-code es
#define XP      136                  // xs pitch in b16 (272B, 16B-aligned rows)
#define EP      264                  // es pitch in b16 (528B)
#define SO_XS   0                    // 256*136*2 = 69632
#define SO_ES   69632                // 64*528    = 33792 (also norm-partial scratch pre-staging)
#define SO_EN   103424               // 1024 floats
#define SO_NORM 107520               // 128 floats
#define SO_FLAG 108032               // cnt + 128 ints
#define SO_IDX  108552               // 128 ints
#define SO_RED  109064               // 8 floats
#define SMEM_TOTAL 110144

// Device scratch
__device__ float          g_enorm[K_CODES];
__device__ __nv_bfloat16  g_eb16[K_CODES * D_DIM];
__device__ float          g_partials[256];
__device__ int            g_hist[K_CODES];

__device__ __forceinline__ float warpReduceSum(float v) {
    #pragma unroll
    for (int o = 16; o > 0; o >>= 1) v += __shfl_down_sync(0xffffffffu, v, o);
    return v;
}
__device__ __forceinline__ uint32_t smem_u32(const void* p) {
    uint32_t a;
    asm("{ .reg .u64 t; cvta.to.shared.u64 t, %1; cvt.u32.u64 %0, t; }" : "=r"(a) : "l"(p));
    return a;
}
__device__ __forceinline__ uint32_t packbf(float lo, float hi) {
    return ((uint32_t)__bfloat16_as_ushort(__float2bfloat16(hi)) << 16)
         |  (uint32_t)__bfloat16_as_ushort(__float2bfloat16(lo));
}

#define LDM_X4_T(r0,r1,r2,r3, a)                                               \
    asm volatile("ldmatrix.sync.aligned.m8n8.x4.trans.shared.b16 {%0,%1,%2,%3}, [%4];" \
                 : "=r"(r0), "=r"(r1), "=r"(r2), "=r"(r3) : "r"(a))
#define LDM_X4(r0,r1,r2,r3, a)                                                 \
    asm volatile("ldmatrix.sync.aligned.m8n8.x4.shared.b16 {%0,%1,%2,%3}, [%4];" \
                 : "=r"(r0), "=r"(r1), "=r"(r2), "=r"(r3) : "r"(a))
#define MMA_BF16(c0,c1,c2,c3, a0,a1,a2,a3, b0,b1)                              \
    asm volatile("mma.sync.aligned.m16n8k16.row.col.f32.bf16.bf16.f32 "        \
                 "{%0,%1,%2,%3},{%4,%5,%6,%7},{%8,%9},{%0,%1,%2,%3};"          \
                 : "+f"(c0), "+f"(c1), "+f"(c2), "+f"(c3)                      \
                 : "r"(a0), "r"(a1), "r"(a2), "r"(a3), "r"(b0), "r"(b1))
#define CP_ASYNC16(dst, src)                                                   \
    asm volatile("cp.async.cg.shared.global [%0], [%1], 16;" :: "r"(dst), "l"(src))
#define CP_COMMIT() asm volatile("cp.async.commit_group;" ::: "memory")
#define CP_WAIT(n)  asm volatile("cp.async.wait_group %0;" :: "n"(n) : "memory")

__device__ __forceinline__ void ins4(float v, int k, float bv[4], int bi[4]) {
    if (v < bv[3] || (v == bv[3] && k < bi[3])) {
        bv[3] = v; bi[3] = k;
        #pragma unroll
        for (int t = 3; t > 0; t--) {
            if (bv[t] < bv[t-1] || (bv[t] == bv[t-1] && bi[t] < bi[t-1])) {
                float tv = bv[t]; bv[t] = bv[t-1]; bv[t-1] = tv;
                int   ti = bi[t]; bi[t] = bi[t-1]; bi[t-1] = ti;
            }
        }
    }
}

// ---------------------------------------------------------------------------
// 1) prep: ||e_k||^2 + e->bf16 + zero hist. grid=128, block=256 (1 warp/code)
// ---------------------------------------------------------------------------
__global__ void prep_kernel(const float* __restrict__ emb) {
    int t = threadIdx.x;
    int lane = t & 31;
    int k = blockIdx.x * 8 + (t >> 5);
    const float4* src = (const float4*)(emb + ((size_t)k << 8));
    float4 a = src[lane * 2];
    float4 c = src[lane * 2 + 1];
    uint4 u;
    u.x = packbf(a.x, a.y); u.y = packbf(a.z, a.w);
    u.z = packbf(c.x, c.y); u.w = packbf(c.z, c.w);
    *(uint4*)(g_eb16 + ((size_t)k << 8) + lane * 8) = u;
    float ss = 0.f;
    ss = fmaf(a.x, a.x, ss); ss = fmaf(a.y, a.y, ss);
    ss = fmaf(a.z, a.z, ss); ss = fmaf(a.w, a.w, ss);
    ss = fmaf(c.x, c.x, ss); ss = fmaf(c.y, c.y, ss);
    ss = fmaf(c.z, c.z, ss); ss = fmaf(c.w, c.w, ss);
    ss = warpReduceSum(ss);
    if (lane == 0) g_enorm[k] = ss;
    if (blockIdx.x == 0) {
        for (int i = t; i < K_CODES; i += 256) g_hist[i] = 0;
    }
}

// ---------------------------------------------------------------------------
// 2) bf16 mma.sync GEMM + best-4/lane + fused exact rescue + gather/SSE/hist.
//    CTA: 128 rows x 1024 codes (16 chunks of 64, single-buffered es).
//    Norms computed IN the fill pass (single DRAM read of x at startup).
//    8 warps = 8 row-groups of 16. grid=256, block=256, 2 CTA/SM -> one wave.
// ---------------------------------------------------------------------------
__global__ void __launch_bounds__(256, 2)
argmin_bf16_kernel(const float* __restrict__ x, const float* __restrict__ embf,
                   float* __restrict__ out, int out_size) {
    extern __shared__ __align__(16) char smem[];
    __nv_bfloat16* xs = (__nv_bfloat16*)(smem + SO_XS);   // [256 d][XP]
    float* en_s  = (float*)(smem + SO_EN);
    float* norms = (float*)(smem + SO_NORM);
    int*   flagc = (int*)(smem + SO_FLAG);
    int*   flagr = flagc + 1;
    int*   idx_s = (int*)(smem + SO_IDX);

    const int tid  = threadIdx.x;
    const int lane = tid & 31;
    const int w    = tid >> 5;           // 0..7 = row group
    const int g4   = lane >> 2;
    const int tg   = lane & 3;
    const int R    = w << 4;
    const int n0   = blockIdx.x << 7;
    const int b    = n0 >> 10;
    const int hw0  = n0 & 1023;
    const float* xb = x + ((size_t)b << 18) + hw0;

    const uint32_t es_u = smem_u32(smem + SO_ES);

    if (tid == 0) *flagc = 0;

    // ---- fill xs (bf16) + fused fp32 norm partials (single x read) ----
    // thread covers fixed 8-row block r8f = (tid&15)*8, d = 16*i + (tid>>4)
    {
        const int r8f = (tid & 15) << 3;
        const int dco = tid >> 4;
        float na8[8];
        #pragma unroll
        for (int j = 0; j < 8; j++) na8[j] = 0.f;
        #pragma unroll
        for (int i = 0; i < 16; i++) {
            int d = (i << 4) + dco;
            float4 t0 = *(const float4*)(xb + ((size_t)d << 10) + r8f);
            float4 t1 = *(const float4*)(xb + ((size_t)d << 10) + r8f + 4);
            na8[0] = fmaf(t0.x, t0.x, na8[0]);
            na8[1] = fmaf(t0.y, t0.y, na8[1]);
            na8[2] = fmaf(t0.z, t0.z, na8[2]);
            na8[3] = fmaf(t0.w, t0.w, na8[3]);
            na8[4] = fmaf(t1.x, t1.x, na8[4]);
            na8[5] = fmaf(t1.y, t1.y, na8[5]);
            na8[6] = fmaf(t1.z, t1.z, na8[6]);
            na8[7] = fmaf(t1.w, t1.w, na8[7]);
            uint4 u;
            u.x = packbf(t0.x, t0.y); u.y = packbf(t0.z, t0.w);
            u.z = packbf(t1.x, t1.y); u.w = packbf(t1.z, t1.w);
            *(uint4*)&xs[d * XP + r8f] = u;
        }
        // partials into es-region scratch [row][16] (staging not yet issued)
        float* scr = (float*)(smem + SO_ES);
        #pragma unroll
        for (int j = 0; j < 8; j++) scr[(r8f + j) * 16 + dco] = na8[j];
    }
    for (int i = tid; i < K_CODES; i += 256) en_s[i] = g_enorm[i];
    __syncthreads();
    if (tid < 128) {
        const float* p = (const float*)(smem + SO_ES) + tid * 16;
        float s = 0.f;
        #pragma unroll
        for (int j = 0; j < 16; j++) s += p[j];
        norms[tid] = s;
    }
    __syncthreads();   // norms done; scratch dead -> safe to stage es

    // ---- stage chunk 0 (64 codes) via cp.async
    #pragma unroll
    for (int it = 0; it < 8; it++) {
        int lin = it * 256 + tid;        // 0..2047
        int c   = lin >> 5;              // code 0..63
        int sg  = lin & 31;              // 16B segment
        CP_ASYNC16(es_u + (uint32_t)(c * (EP * 2) + sg * 16),
                   (const void*)(g_eb16 + ((size_t)c << 8) + sg * 8));
    }
    CP_COMMIT();
    CP_WAIT(0);
    __syncthreads();

    const float na0 = norms[R + g4];
    const float na1 = norms[R + g4 + 8];

    // per-lane ldmatrix addressing
    const uint32_t xs_u = smem_u32(xs);
    const int i8  = lane & 7;
    const int sel = lane >> 3;
    const uint32_t a_base = xs_u
        + (uint32_t)(((i8 + ((sel & 2) ? 8 : 0)) * XP + R + ((sel & 1) ? 8 : 0)) * 2);
    uint32_t b_off[4];
    #pragma unroll
    for (int p = 0; p < 4; p++)
        b_off[p] = (uint32_t)(((p * 16 + i8 + ((sel & 2) ? 8 : 0)) * EP) * 2
                              + ((sel & 1) ? 16 : 0));

    float bva[4], bvb[4]; int bia[4], bib[4];
    #pragma unroll
    for (int j = 0; j < 4; j++) {
        bva[j] = 3.4e38f; bvb[j] = 3.4e38f;
        bia[j] = 0x7fffffff; bib[j] = 0x7fffffff;
    }

    for (int chunk = 0; chunk < 16; chunk++) {
        float acc[8][4];
        #pragma unroll
        for (int j = 0; j < 8; j++)
            #pragma unroll
            for (int q = 0; q < 4; q++) acc[j][q] = 0.f;

        #pragma unroll
        for (int K = 0; K < 256; K += 16) {
            uint32_t a0, a1, a2, a3;
            LDM_X4_T(a0, a1, a2, a3, a_base + (uint32_t)(K * XP * 2));
            #pragma unroll
            for (int p = 0; p < 4; p++) {
                uint32_t r0, r1, r2, r3;
                LDM_X4(r0, r1, r2, r3, es_u + b_off[p] + (uint32_t)(K * 2));
                MMA_BF16(acc[2*p][0], acc[2*p][1], acc[2*p][2], acc[2*p][3],
                         a0, a1, a2, a3, r0, r1);
                MMA_BF16(acc[2*p+1][0], acc[2*p+1][1], acc[2*p+1][2], acc[2*p+1][3],
                         a0, a1, a2, a3, r2, r3);
            }
        }
        __syncthreads();   // all warps done reading es before restage
        if (chunk < 15) {  // stage next chunk (single buffer)
            #pragma unroll
            for (int it = 0; it < 8; it++) {
                int lin = it * 256 + tid;
                int c   = lin >> 5;
                int sg  = lin & 31;
                CP_ASYNC16(es_u + (uint32_t)(c * (EP * 2) + sg * 16),
                           (const void*)(g_eb16 + (((size_t)((chunk + 1) * 64 + c)) << 8) + sg * 8));
            }
            CP_COMMIT();
        }
        // epilogue overlaps the cp.async in flight
        const int kb = chunk * 64;
        #pragma unroll
        for (int j = 0; j < 8; j++) {
            int k0 = kb + (j >> 1) * 16 + (j & 1) * 8 + 2 * tg;
            float e0 = en_s[k0], e1 = en_s[k0 + 1];
            ins4(fmaf(-2.f, acc[j][0], na0 + e0), k0,     bva, bia);
            ins4(fmaf(-2.f, acc[j][1], na0 + e1), k0 + 1, bva, bia);
            ins4(fmaf(-2.f, acc[j][2], na1 + e0), k0,     bvb, bib);
            ins4(fmaf(-2.f, acc[j][3], na1 + e1), k0 + 1, bvb, bib);
        }
        if (chunk < 15) CP_WAIT(0);
        __syncthreads();
    }

    // ---- candidate staging (alias es; all MMA reads done) ----
    float* cand_v = (float*)(smem + SO_ES);              // [128][16]
    int*   cand_i = (int*)(smem + SO_ES + 8192);
    {
        int ra = R + g4, rb = R + g4 + 8;
        int s0 = tg * 4;
        #pragma unroll
        for (int j = 0; j < 4; j++) {
            cand_v[ra * 16 + s0 + j] = bva[j];
            cand_i[ra * 16 + s0 + j] = bia[j];
            cand_v[rb * 16 + s0 + j] = bvb[j];
            cand_i[rb * 16 + s0 + j] = bib[j];
        }
    }
    __syncthreads();

    // ---- decision per row ----
    if (tid < 128) {
        int r = tid;
        float vm = cand_v[r * 16]; int im = cand_i[r * 16];
        #pragma unroll
        for (int j = 1; j < 16; j++) {
            float v = cand_v[r * 16 + j]; int k = cand_i[r * 16 + j];
            if (v < vm || (v == vm && k < im)) { vm = v; im = k; }
        }
        int cnt = 0;
        #pragma unroll
        for (int j = 0; j < 16; j++) cnt += (cand_v[r * 16 + j] <= vm + TAU);
        if (cnt == 1) {
            idx_s[r] = im;
        } else {
            int slot = atomicAdd(flagc, 1);
            flagr[slot] = r;
        }
    }
    __syncthreads();

    // ---- fused exact rescue: warp per flagged row ----
    const int nflag = *flagc;
    for (int f = w; f < nflag; f += 8) {
        int r = flagr[f];
        const float* xr = xb + r;
        float xv[8];
        #pragma unroll
        for (int t = 0; t < 8; t++) xv[t] = xr[(size_t)(lane + (t << 5)) << 10];
        float a = norms[r];   // exact fp32 (translation-invariant vs reference)

        float vmin = cand_v[r * 16];
        #pragma unroll
        for (int j = 1; j < 16; j++) vmin = fminf(vmin, cand_v[r * 16 + j]);

        float bestv = 3.4e38f; int besti = 0x7fffffff;
        for (int j = 0; j < 16; j++) {
            float cv = cand_v[r * 16 + j];
            if (cv > vmin + TAU) continue;
            int k = cand_i[r * 16 + j];
            const float* er = embf + ((size_t)k << 8);
            float d = 0.f;
            #pragma unroll
            for (int t = 0; t < 8; t++) d = fmaf(xv[t], er[lane + (t << 5)], d);
            #pragma unroll
            for (int o = 16; o > 0; o >>= 1) d += __shfl_xor_sync(0xffffffffu, d, o);
            float vv = fmaf(-2.f, d, a + en_s[k]);   // fl(fl(a+b) - 2*dot)
            if (vv < bestv || (vv == bestv && k < besti)) { bestv = vv; besti = k; }
        }
        if (lane == 0) idx_s[r] = besti;
    }
    __syncthreads();

    // ---- fused hist + index writeout ----
    if (tid < 128) {
        int idx = idx_s[tid];
        atomicAdd(&g_hist[idx], 1);
        if (out_size >= Q_ELEMS + 2 + N_TOT)
            out[Q_ELEMS + 2 + n0 + tid] = (float)idx;
    }

    // ---- fused gather + SSE for this CTA's 128 rows ----
    float sse = 0.f;
    #pragma unroll
    for (int u = 0; u < 32; u++) {
        int lin = u * 256 + tid;          // 0..8191
        int r   = lin & 127;
        int d4  = lin >> 7;               // 0..63
        int idx = idx_s[r];
        float4 q = *(const float4*)(embf + ((size_t)idx << 8) + (d4 << 2));
        const float* xp = xb + ((size_t)(d4 << 2) << 10) + r;
        float* op = out + ((size_t)b << 18) + ((size_t)(d4 << 2) << 10) + hw0 + r;
        float qv[4] = {q.x, q.y, q.z, q.w};
        #pragma unroll
        for (int j = 0; j < 4; j++) {
            float xvj = xp[(size_t)j << 10];
            op[(size_t)j << 10] = qv[j];
            float dd = qv[j] - xvj;
            sse = fmaf(dd, dd, sse);
        }
    }
    {
        float* red = (float*)(smem + SO_RED);
        sse = warpReduceSum(sse);
        if (lane == 0) red[w] = sse;
        __syncthreads();
        if (tid < 8) {
            float v = red[tid];
            #pragma unroll
            for (int o = 4; o > 0; o >>= 1) v += __shfl_down_sync(0xffu, v, o);
            if (tid == 0) g_partials[blockIdx.x] = v;
        }
    }
}

// ---------------------------------------------------------------------------
// 3) finalize: loss + perplexity. grid=1, block=1024
// ---------------------------------------------------------------------------
__global__ void finalize_kernel(float* __restrict__ out, int out_size) {
    __shared__ float red[32];
    int tid = threadIdx.x;
    float s = (tid < 256) ? g_partials[tid] : 0.f;
    s = warpReduceSum(s);
    if ((tid & 31) == 0) red[tid >> 5] = s;
    __syncthreads();
    if (tid < 32) {
        float v = red[tid];
        v = warpReduceSum(v);
        if (tid == 0 && out_size > Q_ELEMS)
            out[Q_ELEMS] = 1.25f * v / (float)Q_ELEMS;   // q_latent + 0.25*e_latent
    }
    __syncthreads();
    float p = (float)g_hist[tid] / (float)N_TOT;
    float t = -p * logf(p + 1e-10f);
    t = warpReduceSum(t);
    if ((tid & 31) == 0) red[tid >> 5] = t;
    __syncthreads();
    if (tid < 32) {
        float v = red[tid];
        v = warpReduceSum(v);
        if (tid == 0 && out_size > Q_ELEMS + 1)
            out[Q_ELEMS + 1] = expf(v);
    }
}

// ---------------------------------------------------------------------------
extern "C" void kernel_launch(void* const* d_in, const int* in_sizes, int n_in,
                              void* d_out, int out_size) {
    const float* inputs = (const float*)d_in[0];
    const float* emb    = (const float*)d_in[1];
    if (n_in >= 2 && in_sizes[0] == K_CODES * D_DIM && in_sizes[1] == Q_ELEMS) {
        const float* t = inputs; inputs = emb; emb = t;
    }
    float* out = (float*)d_out;

    cudaFuncSetAttribute(argmin_bf16_kernel,
                         cudaFuncAttributeMaxDynamicSharedMemorySize, SMEM_TOTAL);

    prep_kernel<<<K_CODES / 8, 256>>>(emb);
    argmin_bf16_kernel<<<N_TOT / 128, 256, SMEM_TOTAL>>>(inputs, emb, out, out_size);
    finalize_kernel<<<1, 1024>>>(out, out_size);
}